// round 16
// baseline (speedup 1.0000x reference)
#include <cuda_runtime.h>
#include <cstdint>

#define Bn 16
#define Tn 512
#define En 2048
#define Hn 1024
#define Dn 128

// ---------------- scratch (device globals; no allocs allowed) ----------------
__device__ float        g_xw[(size_t)Bn * Tn * Hn];   // 32 MB: x@W_ih^T + biases
__device__ float        g_h[2][Hn];                   // double-buffered hidden state
__device__ float        g_hs[Bn * Hn];                // per-batch final hidden
__device__ unsigned int g_ctr;                        // RNN grid barrier counter
__device__ unsigned int g_bdone[Bn];                  // per-batch completed GEMM tiles

// ---------------- init: must reset per launch (graph replays) ----------------
__global__ void init_kernel() {
    int tid = blockIdx.x * blockDim.x + threadIdx.x;
    if (tid < 2 * Hn) ((float*)g_h)[tid] = 0.0f;
    if (tid == 0) g_ctr = 0u;
    if (tid < Bn) g_bdone[tid] = 0u;
}

// ---------------- 64x64x2048 fp32 GEMM tile, 256 threads ----------------------
#define GM 64
#define GN 64
#define GK 16
#define GSP 68   // padded smem stride (floats)

__device__ __forceinline__ void gemm_tile_64(
    float* As, float* Bs,
    const float* __restrict__ X, const float* __restrict__ Wih,
    const float* __restrict__ bih, const float* __restrict__ bhh,
    int b, int mt, int nt, int tid)
{
    const int tx   = tid & 15;        // n: 4 cols each
    const int ty   = tid >> 4;        // m: 4 rows each (16 groups)
    const int row0 = b * Tn + mt * GM;
    const int n0   = nt * GN;

    float acc[4][4];
#pragma unroll
    for (int i = 0; i < 4; i++)
#pragma unroll
        for (int j = 0; j < 4; j++) acc[i][j] = 0.0f;

    for (int k0 = 0; k0 < En; k0 += GK) {
        {   // 256 float4 per matrix, 256 threads: one each
            int m  = tid >> 2;                 // 0..63
            int kq = (tid & 3) << 2;           // 0,4,8,12
            float4 av = *(const float4*)&X  [(size_t)(row0 + m) * En + k0 + kq];
            float4 bv = *(const float4*)&Wih[(size_t)(n0  + m) * En + k0 + kq];
            As[(kq + 0) * GSP + m] = av.x; As[(kq + 1) * GSP + m] = av.y;
            As[(kq + 2) * GSP + m] = av.z; As[(kq + 3) * GSP + m] = av.w;
            Bs[(kq + 0) * GSP + m] = bv.x; Bs[(kq + 1) * GSP + m] = bv.y;
            Bs[(kq + 2) * GSP + m] = bv.z; Bs[(kq + 3) * GSP + m] = bv.w;
        }
        __syncthreads();
#pragma unroll
        for (int k = 0; k < GK; k++) {
            float4 bv = *(const float4*)&Bs[k * GSP + 4 * tx];
            float4 a0 = *(const float4*)&As[k * GSP + 4 * ty];
            float ar[4] = {a0.x, a0.y, a0.z, a0.w};
#pragma unroll
            for (int i = 0; i < 4; i++) {
                acc[i][0] = fmaf(ar[i], bv.x, acc[i][0]);
                acc[i][1] = fmaf(ar[i], bv.y, acc[i][1]);
                acc[i][2] = fmaf(ar[i], bv.z, acc[i][2]);
                acc[i][3] = fmaf(ar[i], bv.w, acc[i][3]);
            }
        }
        __syncthreads();
    }

    float4 bi = *(const float4*)&bih[n0 + 4 * tx];
    float4 bh = *(const float4*)&bhh[n0 + 4 * tx];
    float4 c  = make_float4(bi.x + bh.x, bi.y + bh.y, bi.z + bh.z, bi.w + bh.w);
#pragma unroll
    for (int i = 0; i < 4; i++) {
        int m = 4 * ty + i;
        float4 o = make_float4(acc[i][0] + c.x, acc[i][1] + c.y,
                               acc[i][2] + c.z, acc[i][3] + c.w);
        *(float4*)&g_xw[(size_t)(row0 + m) * Hn + n0 + 4 * tx] = o;
    }
}

// ---------------- batch-0 GEMM: runs before rnn (stream order = ready) --------
__global__ __launch_bounds__(256, 1) void xw_gemm_b0(
    const float* __restrict__ X, const float* __restrict__ Wih,
    const float* __restrict__ bih, const float* __restrict__ bhh,
    const int* __restrict__ lengths)
{
    __shared__ __align__(16) float As[GK * GSP];
    __shared__ __align__(16) float Bs[GK * GSP];
    const int mt = blockIdx.x & 7;     // grid 128 = 8 mt x 16 nt
    const int nt = blockIdx.x >> 3;
    if (mt * GM >= lengths[0]) return; // fully-padded tile: never read
    gemm_tile_64(As, Bs, X, Wih, bih, bhh, 0, mt, nt, threadIdx.x);
}

// ---------------- fast tanh: 1 - 2/(e^{2x}+1); abs err ~1e-6 (R7-proven) ------
__device__ __forceinline__ float ftanh(float x) {
    float e = __expf(2.0f * x);
    return 1.0f - __fdividef(2.0f, e + 1.0f);
}

// ---------------- fused RNN + side-GEMM ---------------------------------------
// Grid = 148 CTAs x 256 threads, all co-resident (1/SM).
//   CTAs 0..127  : RNN, R15 protocol skeleton (measured-best) with two cuts:
//     (a) ONE ROW PER WARP (8 warps): per-lane FMA 64->32, W-regs 64->32,
//         tail = one tanh. Same 128-CTA topology (R10 showed CTA count must
//         stay 128); only intra-CTA width changes.
//     (b) NO per-warp __threadfence: stores -> __syncthreads -> tid0
//         red.release.gpu.add publishes all 8 warps' h stores (bar gives
//         intra-CTA happens-before; release orders them before the counter
//         increment). Consumer side: tid0 acquire-poll as before.
//   CTAs 128..147: GEMM workers for batches 1..15 (hidden under the RNN).
// Protocol: stage h -> bar -> matvec -> lane0 store -> bar ->
//           tid0 red.release + acquire-poll -> bar.
#define NBLK  128
#define NWORK 20
#define RPC   8

__global__ __launch_bounds__(256, 1) void rnn_fused(
    const float* __restrict__ Whh, const float* __restrict__ X,
    const float* __restrict__ Wih, const float* __restrict__ bih,
    const float* __restrict__ bhh, const int* __restrict__ lengths)
{
    __shared__ __align__(16) float hsh[Hn];        // RNN: 4 KB staged h
    __shared__ __align__(16) float As[GK * GSP];   // worker tiles
    __shared__ __align__(16) float Bs[GK * GSP];

    const int tid = threadIdx.x;
    const int cta = blockIdx.x;

    if (cta >= NBLK) {
        // ---------------- GEMM worker role ----------------
        const int widx = cta - NBLK;
        int g = 0;
        for (int b = 1; b < Bn; b++) {
            const int L     = __ldg(&lengths[b]);
            const int ntile = ((L + 63) >> 6) * 16;
            for (int ti = 0; ti < ntile; ti++, g++) {
                if (g % NWORK != widx) continue;
                gemm_tile_64(As, Bs, X, Wih, bih, bhh, b, ti >> 4, ti & 15, tid);
                __syncthreads();   // all threads' xw stores precede the release
                if (tid == 0)
                    asm volatile("red.release.gpu.global.add.u32 [%0], %1;"
                                 :: "l"(&g_bdone[b]), "r"(1u) : "memory");
            }
        }
        return;
    }

    // ---------------- RNN role: 8 warps, ONE row per warp ----------------
    const int w    = tid >> 5;
    const int lane = tid & 31;
    const int gr   = cta * RPC + w;   // this warp's output row

    // one-time: W_hh row into registers (per j, warp reads 128B contiguous)
    float wr[32];
#pragma unroll
    for (int j = 0; j < 32; j++)
        wr[j] = __ldg(&Whh[(size_t)gr * Hn + lane + 32 * j]);

    unsigned int step = 0;
    for (int b = 0; b < Bn; b++) {
        const int L = __ldg(&lengths[b]);
        const float* xwb = g_xw + (size_t)b * Tn * Hn;

        // gate: batch b's xw tiles must be complete (b=0 done pre-launch)
        if (b > 0) {
            if (tid == 0) {
                const unsigned int ntile = (unsigned int)(((L + 63) >> 6) * 16);
                unsigned int v;
                do {
                    asm volatile("ld.acquire.gpu.global.u32 %0, [%1];"
                                 : "=r"(v) : "l"(&g_bdone[b]) : "memory");
                } while (v < ntile);
            }
            __syncthreads();
        }

        for (int t = 0; t < L; t++) {
            const float* hread  = g_h[step & 1u];
            float*       hwrite = g_h[(step & 1u) ^ 1u];

            // prefetch this step's xw value early (overlaps stage latency)
            float xwv = 0.0f;
            if (lane == 0) xwv = __ldcg(&xwb[(size_t)t * Hn + gr]);

            // stage h: ONE float4 per thread (256 x 16B = 4KB)
            ((float4*)hsh)[tid] = __ldcg(&((const float4*)hread)[tid]);
            __syncthreads();

            // matvec from registers: 32 FMA + 32 conflict-free LDS.32
            float a0 = 0.f, a1 = 0.f, a2 = 0.f, a3 = 0.f;
#pragma unroll
            for (int j = 0; j < 32; j += 4) {
                a0 = fmaf(hsh[lane + 32 * j],       wr[j],     a0);
                a1 = fmaf(hsh[lane + 32 * (j + 1)], wr[j + 1], a1);
                a2 = fmaf(hsh[lane + 32 * (j + 2)], wr[j + 2], a2);
                a3 = fmaf(hsh[lane + 32 * (j + 3)], wr[j + 3], a3);
            }
            float s = (a0 + a1) + (a2 + a3);
#pragma unroll
            for (int off = 16; off > 0; off >>= 1)
                s += __shfl_xor_sync(0xffffffffu, s, off);

            if (lane == 0) {
                float hn = ftanh(xwv + s);
                __stcg(&hwrite[gr], hn);
                if (t == L - 1) __stcg(&g_hs[b * Hn + gr], hn);
            }
            __syncthreads();   // all 8 warps' stores precede the release

            // grid barrier over the 128 RNN CTAs (release-add, no fence)
            if (tid == 0) {
                asm volatile("red.release.gpu.global.add.u32 [%0], %1;"
                             :: "l"(&g_ctr), "r"(1u) : "memory");
                const unsigned int target = (step + 1u) * NBLK;
                unsigned int v;
                do {
                    asm volatile("ld.acquire.gpu.global.u32 %0, [%1];"
                                 : "=r"(v) : "l"(&g_ctr) : "memory");
                } while (v < target);
            }
            __syncthreads();
            step++;
        }
    }
}

// ---------------- head: out[16,128] = hs @ W_l1^T + b_l1 ----------------------
__global__ void head_kernel(const float* __restrict__ Wl1,
                            const float* __restrict__ bl1,
                            float* __restrict__ out)
{
    const int b = blockIdx.x;
    const int d = threadIdx.x;   // 128
    __shared__ float hsh[Hn];
    for (int i = d; i < Hn; i += Dn) hsh[i] = g_hs[b * Hn + i];
    __syncthreads();

    float acc = bl1[d];
    const float* wr = Wl1 + (size_t)d * Hn;
#pragma unroll 4
    for (int k = 0; k < Hn; k += 4) {
        float4 wv = *(const float4*)&wr[k];
        acc = fmaf(wv.x, hsh[k + 0], acc);
        acc = fmaf(wv.y, hsh[k + 1], acc);
        acc = fmaf(wv.z, hsh[k + 2], acc);
        acc = fmaf(wv.w, hsh[k + 3], acc);
    }
    out[b * Dn + d] = acc;
}

// ---------------- launch ------------------------------------------------------
extern "C" void kernel_launch(void* const* d_in, const int* in_sizes, int n_in,
                              void* d_out, int out_size)
{
    const float* x       = (const float*)d_in[0];
    const int*   lengths = (const int*)  d_in[1];
    const float* W_ih    = (const float*)d_in[2];
    const float* W_hh    = (const float*)d_in[3];
    const float* b_ih    = (const float*)d_in[4];
    const float* b_hh    = (const float*)d_in[5];
    const float* W_l1    = (const float*)d_in[6];
    const float* b_l1    = (const float*)d_in[7];
    float* out = (float*)d_out;

    init_kernel<<<8, 256>>>();

    // batch 0 only: done before rnn starts (stream order)
    xw_gemm_b0<<<128, 256>>>(x, W_ih, b_ih, b_hh, lengths);

    // fused: 128 RNN CTAs + 20 GEMM-worker CTAs (batches 1..15, overlapped)
    rnn_fused<<<NBLK + NWORK, 256>>>(W_hh, x, W_ih, b_ih, b_hh, lengths);

    head_kernel<<<Bn, Dn>>>(W_l1, b_l1, out);
}

// round 17
// speedup vs baseline: 1.0332x; 1.0332x over previous
#include <cuda_runtime.h>
#include <cstdint>

#define Bn 16
#define Tn 512
#define En 2048
#define Hn 1024
#define Dn 128

// ---------------- scratch (device globals; no allocs allowed) ----------------
__device__ float        g_xw[(size_t)Bn * Tn * Hn];   // 32 MB: x@W_ih^T + biases
__device__ float        g_h[2][Hn];                   // double-buffered hidden state
__device__ float        g_hs[Bn * Hn];                // per-batch final hidden
__device__ unsigned int g_ctr;                        // RNN grid barrier counter
__device__ unsigned int g_bdone[Bn];                  // per-batch completed GEMM tiles

// ---------------- init: must reset per launch (graph replays) ----------------
__global__ void init_kernel() {
    int tid = blockIdx.x * blockDim.x + threadIdx.x;
    if (tid < 2 * Hn) ((float*)g_h)[tid] = 0.0f;
    if (tid == 0) g_ctr = 0u;
    if (tid < Bn) g_bdone[tid] = 0u;
}

// ---------------- no-op pad kernels: shift rnn_fused to ncu capture index 5 ---
__global__ void pad_kernel() {}

// ---------------- 64x64x2048 fp32 GEMM tile, 128 threads ----------------------
#define GM 64
#define GN 64
#define GK 16
#define GSP 68   // padded smem stride (floats)

__device__ __forceinline__ void gemm_tile_64(
    float* As, float* Bs,
    const float* __restrict__ X, const float* __restrict__ Wih,
    const float* __restrict__ bih, const float* __restrict__ bhh,
    int b, int mt, int nt, int tid)
{
    const int tx   = tid & 15;        // n: 4 cols each
    const int ty   = tid >> 4;        // m: 8 rows each
    const int row0 = b * Tn + mt * GM;
    const int n0   = nt * GN;

    float acc[8][4];
#pragma unroll
    for (int i = 0; i < 8; i++)
#pragma unroll
        for (int j = 0; j < 4; j++) acc[i][j] = 0.0f;

    for (int k0 = 0; k0 < En; k0 += GK) {
#pragma unroll
        for (int i = 0; i < 2; i++) {             // 256 float4 per matrix / 128 thr
            int idx = tid + i * 128;
            int m   = idx >> 2;                   // 0..63
            int kq  = (idx & 3) << 2;             // 0,4,8,12
            float4 av = *(const float4*)&X  [(size_t)(row0 + m) * En + k0 + kq];
            float4 bv = *(const float4*)&Wih[(size_t)(n0  + m) * En + k0 + kq];
            As[(kq + 0) * GSP + m] = av.x; As[(kq + 1) * GSP + m] = av.y;
            As[(kq + 2) * GSP + m] = av.z; As[(kq + 3) * GSP + m] = av.w;
            Bs[(kq + 0) * GSP + m] = bv.x; Bs[(kq + 1) * GSP + m] = bv.y;
            Bs[(kq + 2) * GSP + m] = bv.z; Bs[(kq + 3) * GSP + m] = bv.w;
        }
        __syncthreads();
#pragma unroll
        for (int k = 0; k < GK; k++) {
            float4 bv = *(const float4*)&Bs[k * GSP + 4 * tx];
            float4 a0 = *(const float4*)&As[k * GSP + 8 * ty];
            float4 a1 = *(const float4*)&As[k * GSP + 8 * ty + 4];
            float ar[8] = {a0.x, a0.y, a0.z, a0.w, a1.x, a1.y, a1.z, a1.w};
#pragma unroll
            for (int i = 0; i < 8; i++) {
                acc[i][0] = fmaf(ar[i], bv.x, acc[i][0]);
                acc[i][1] = fmaf(ar[i], bv.y, acc[i][1]);
                acc[i][2] = fmaf(ar[i], bv.z, acc[i][2]);
                acc[i][3] = fmaf(ar[i], bv.w, acc[i][3]);
            }
        }
        __syncthreads();
    }

    float4 bi = *(const float4*)&bih[n0 + 4 * tx];
    float4 bh = *(const float4*)&bhh[n0 + 4 * tx];
    float4 c  = make_float4(bi.x + bh.x, bi.y + bh.y, bi.z + bh.z, bi.w + bh.w);
#pragma unroll
    for (int i = 0; i < 8; i++) {
        int m = 8 * ty + i;
        float4 o = make_float4(acc[i][0] + c.x, acc[i][1] + c.y,
                               acc[i][2] + c.z, acc[i][3] + c.w);
        *(float4*)&g_xw[(size_t)(row0 + m) * Hn + n0 + 4 * tx] = o;
    }
}

// ---------------- batch-0 GEMM: runs before rnn (stream order = ready) --------
__global__ __launch_bounds__(128, 1) void xw_gemm_b0(
    const float* __restrict__ X, const float* __restrict__ Wih,
    const float* __restrict__ bih, const float* __restrict__ bhh,
    const int* __restrict__ lengths)
{
    __shared__ __align__(16) float As[GK * GSP];
    __shared__ __align__(16) float Bs[GK * GSP];
    const int mt = blockIdx.x & 7;     // grid 128 = 8 mt x 16 nt
    const int nt = blockIdx.x >> 3;
    if (mt * GM >= lengths[0]) return; // fully-padded tile: never read
    gemm_tile_64(As, Bs, X, Wih, bih, bhh, 0, mt, nt, threadIdx.x);
}

// ---------------- fast tanh: 1 - 2/(e^{2x}+1); abs err ~1e-6 (R7-proven) ------
__device__ __forceinline__ float ftanh(float x) {
    float e = __expf(2.0f * x);
    return 1.0f - __fdividef(2.0f, e + 1.0f);
}

// ---------------- fused RNN + side-GEMM ---------------------------------------
// Grid = 148 CTAs x 128 threads, all co-resident (1/SM).
//   CTAs 0..127  : R15's RNN byte-for-byte (measured best, 1.77us/step) with
//     ONE isolated change (the R16-(b) fence-cut, deconfounded from the width
//     change that regressed): per-warp __threadfence removed; publication is
//     lane0 stores -> __syncthreads -> tid0 red.release.gpu.add. The bar gives
//     intra-CTA happens-before from all 4 warps' h stores to tid0; the release
//     orders them before the counter increment; consumers acquire-poll as
//     before. Removes 4 MEMBAR.GPUs/CTA/step and the 318cyc atomic return.
//   CTAs 128..147: GEMM workers for batches 1..15 (hidden under the RNN).
#define NBLK  128
#define NWORK 20
#define RPC   8

__global__ __launch_bounds__(128, 1) void rnn_fused(
    const float* __restrict__ Whh, const float* __restrict__ X,
    const float* __restrict__ Wih, const float* __restrict__ bih,
    const float* __restrict__ bhh, const int* __restrict__ lengths)
{
    __shared__ __align__(16) float hsh[Hn];        // RNN: 4 KB staged h
    __shared__ __align__(16) float As[GK * GSP];   // worker tiles
    __shared__ __align__(16) float Bs[GK * GSP];

    const int tid = threadIdx.x;
    const int cta = blockIdx.x;

    if (cta >= NBLK) {
        // ---------------- GEMM worker role ----------------
        const int widx = cta - NBLK;
        int g = 0;
        for (int b = 1; b < Bn; b++) {
            const int L     = __ldg(&lengths[b]);
            const int ntile = ((L + 63) >> 6) * 16;
            for (int ti = 0; ti < ntile; ti++, g++) {
                if (g % NWORK != widx) continue;
                gemm_tile_64(As, Bs, X, Wih, bih, bhh, b, ti >> 4, ti & 15, tid);
                __syncthreads();   // all threads' xw stores precede the release
                if (tid == 0)
                    asm volatile("red.release.gpu.global.add.u32 [%0], %1;"
                                 :: "l"(&g_bdone[b]), "r"(1u) : "memory");
            }
        }
        return;
    }

    // ---------------- RNN role (R15 core: 4 warps, 2 rows/warp) ----------------
    const int w    = tid >> 5;
    const int lane = tid & 31;
    const int gr0  = cta * RPC + 2 * w;   // this warp's two output rows
    const int gr1  = gr0 + 1;

    // one-time: W_hh rows into registers (per j, warp reads 128B contiguous)
    float wr0[32], wr1[32];
#pragma unroll
    for (int j = 0; j < 32; j++) {
        wr0[j] = __ldg(&Whh[(size_t)gr0 * Hn + lane + 32 * j]);
        wr1[j] = __ldg(&Whh[(size_t)gr1 * Hn + lane + 32 * j]);
    }

    unsigned int step = 0;
    for (int b = 0; b < Bn; b++) {
        const int L = __ldg(&lengths[b]);
        const float* xwb = g_xw + (size_t)b * Tn * Hn;

        // gate: batch b's xw tiles must be complete (b=0 done pre-launch)
        if (b > 0) {
            if (tid == 0) {
                const unsigned int ntile = (unsigned int)(((L + 63) >> 6) * 16);
                unsigned int v;
                do {
                    asm volatile("ld.acquire.gpu.global.u32 %0, [%1];"
                                 : "=r"(v) : "l"(&g_bdone[b]) : "memory");
                } while (v < ntile);
            }
            __syncthreads();
        }

        for (int t = 0; t < L; t++) {
            const float* hread  = g_h[step & 1u];
            float*       hwrite = g_h[(step & 1u) ^ 1u];

            // prefetch this step's xw values early (used ~400cyc later)
            float2 xwv = make_float2(0.f, 0.f);
            if (lane == 0)
                xwv = __ldcg((const float2*)&xwb[(size_t)t * Hn + gr0]);

            // stage h (L2 loads: written by other SMs last step)
            const float4* hr4 = (const float4*)hread;
            float4 h0 = __ldcg(&hr4[tid]);
            float4 h1 = __ldcg(&hr4[tid + 128]);
            ((float4*)hsh)[tid]       = h0;
            ((float4*)hsh)[tid + 128] = h1;
            __syncthreads();

            // matvec from registers: 64 FMA + 32 conflict-free LDS.32
            float a0 = 0.f, a1 = 0.f, b0 = 0.f, b1 = 0.f;
#pragma unroll
            for (int j = 0; j < 32; j += 2) {
                float hA = hsh[lane + 32 * j];
                float hB = hsh[lane + 32 * (j + 1)];
                a0 = fmaf(hA, wr0[j],     a0);
                b0 = fmaf(hA, wr1[j],     b0);
                a1 = fmaf(hB, wr0[j + 1], a1);
                b1 = fmaf(hB, wr1[j + 1], b1);
            }
            float sA = a0 + a1;
            float sB = b0 + b1;
#pragma unroll
            for (int off = 16; off > 0; off >>= 1) {
                sA += __shfl_xor_sync(0xffffffffu, sA, off);
                sB += __shfl_xor_sync(0xffffffffu, sB, off);
            }

            if (lane == 0) {
                float hn0 = ftanh(xwv.x + sA);
                float hn1 = ftanh(xwv.y + sB);
                __stcg((float2*)&hwrite[gr0], make_float2(hn0, hn1));
                if (t == L - 1)
                    __stcg((float2*)&g_hs[b * Hn + gr0], make_float2(hn0, hn1));
                // no __threadfence: bar + release below publish the stores
            }
            __syncthreads();   // all 4 warps' stores precede the release

            // grid barrier over the 128 RNN CTAs (release-add, no fence)
            if (tid == 0) {
                asm volatile("red.release.gpu.global.add.u32 [%0], %1;"
                             :: "l"(&g_ctr), "r"(1u) : "memory");
                const unsigned int target = (step + 1u) * NBLK;
                unsigned int v;
                do {
                    asm volatile("ld.acquire.gpu.global.u32 %0, [%1];"
                                 : "=r"(v) : "l"(&g_ctr) : "memory");
                } while (v < target);
            }
            __syncthreads();
            step++;
        }
    }
}

// ---------------- head: out[16,128] = hs @ W_l1^T + b_l1 ----------------------
__global__ void head_kernel(const float* __restrict__ Wl1,
                            const float* __restrict__ bl1,
                            float* __restrict__ out)
{
    const int b = blockIdx.x;
    const int d = threadIdx.x;   // 128
    __shared__ float hsh[Hn];
    for (int i = d; i < Hn; i += Dn) hsh[i] = g_hs[b * Hn + i];
    __syncthreads();

    float acc = bl1[d];
    const float* wr = Wl1 + (size_t)d * Hn;
#pragma unroll 4
    for (int k = 0; k < Hn; k += 4) {
        float4 wv = *(const float4*)&wr[k];
        acc = fmaf(wv.x, hsh[k + 0], acc);
        acc = fmaf(wv.y, hsh[k + 1], acc);
        acc = fmaf(wv.z, hsh[k + 2], acc);
        acc = fmaf(wv.w, hsh[k + 3], acc);
    }
    out[b * Dn + d] = acc;
}

// ---------------- launch ------------------------------------------------------
extern "C" void kernel_launch(void* const* d_in, const int* in_sizes, int n_in,
                              void* d_out, int out_size)
{
    const float* x       = (const float*)d_in[0];
    const int*   lengths = (const int*)  d_in[1];
    const float* W_ih    = (const float*)d_in[2];
    const float* W_hh    = (const float*)d_in[3];
    const float* b_ih    = (const float*)d_in[4];
    const float* b_hh    = (const float*)d_in[5];
    const float* W_l1    = (const float*)d_in[6];
    const float* b_l1    = (const float*)d_in[7];
    float* out = (float*)d_out;

    init_kernel<<<8, 256>>>();                               // launch 0

    // batch 0 only: done before rnn starts (stream order)
    xw_gemm_b0<<<128, 128>>>(x, W_ih, b_ih, b_hh, lengths);  // launch 1

    // pads: put rnn_fused at launch index 5, where ncu -s5 -c1 captures
    pad_kernel<<<1, 32>>>();                                 // launch 2
    pad_kernel<<<1, 32>>>();                                 // launch 3
    pad_kernel<<<1, 32>>>();                                 // launch 4

    // fused: 128 RNN CTAs + 20 GEMM-worker CTAs (batches 1..15, overlapped)
    rnn_fused<<<NBLK + NWORK, 128>>>(W_hh, x, W_ih, b_ih, b_hh, lengths); // 5

    head_kernel<<<Bn, Dn>>>(W_l1, b_l1, out);                // launch 6
}